// round 6
// baseline (speedup 1.0000x reference)
#include <cuda_runtime.h>

#define NN   50000
#define EE   300000
#define ETOT 900000
#define CC   2
#define TT   3
#define HD   64
// scan config
#define SCAN_T 512
#define SCAN_I 8
#define SCAN_CHUNK (SCAN_T * SCAN_I)   // 4096

// ---------------- device scratch (static, allowed) ----------------
__device__ int   g_cnt[NN];
__device__ int   g_rowptr[NN + 1];
__device__ int   g_cursor[NN];
__device__ int   g_bsum[64];
__device__ int   g_scol[ETOT];            // col | (etype<<28)
__device__ float g_sval[ETOT];
__device__ float g_H0[(size_t)CC * NN * HD];
__device__ float g_H1[(size_t)CC * NN * HD];
__device__ float g_X0[(size_t)CC * NN * HD];
__device__ float g_mid[(size_t)NN * HD];

// ---------------- CSR build ----------------
__global__ void k_zero_cnt() {
    int i = blockIdx.x * blockDim.x + threadIdx.x;
    if (i < NN) g_cnt[i] = 0;
}

__global__ void k_hist(const int* __restrict__ ei0, const int* __restrict__ ei1,
                       const int* __restrict__ ei2) {
    int e = blockIdx.x * blockDim.x + threadIdx.x;
    if (e >= ETOT) return;
    const int* ei; int le;
    if (e < EE)           { ei = ei0; le = e; }
    else if (e < 2 * EE)  { ei = ei1; le = e - EE; }
    else                  { ei = ei2; le = e - 2 * EE; }
    atomicAdd(&g_cnt[ei[le]], 1);
}

__global__ void k_scan1() {
    __shared__ int s[SCAN_T];
    int t = threadIdx.x;
    int base = blockIdx.x * SCAN_CHUNK + t * SCAN_I;
    int v[SCAN_I];
    int sum = 0;
#pragma unroll
    for (int i = 0; i < SCAN_I; i++) {
        int idx = base + i;
        v[i] = (idx < NN) ? g_cnt[idx] : 0;
        sum += v[i];
    }
    s[t] = sum;
    __syncthreads();
    for (int off = 1; off < SCAN_T; off <<= 1) {
        int x = (t >= off) ? s[t - off] : 0;
        __syncthreads();
        if (t >= off) s[t] += x;
        __syncthreads();
    }
    int excl = s[t] - sum;
    if (t == SCAN_T - 1) g_bsum[blockIdx.x] = s[t];
    int run = excl;
#pragma unroll
    for (int i = 0; i < SCAN_I; i++) {
        int idx = base + i;
        if (idx < NN) g_rowptr[idx] = run;
        run += v[i];
    }
}

__global__ void k_scan2(int nb) {
    if (threadIdx.x == 0 && blockIdx.x == 0) {
        int run = 0;
        for (int b = 0; b < nb; b++) {
            int x = g_bsum[b];
            g_bsum[b] = run;
            run += x;
        }
        g_rowptr[NN] = ETOT;
    }
}

__global__ void k_scan3() {
    int i = blockIdx.x * blockDim.x + threadIdx.x;
    if (i >= NN) return;
    int val = g_rowptr[i] + g_bsum[i / SCAN_CHUNK];
    g_rowptr[i] = val;
    g_cursor[i] = val;
}

__global__ void k_scatter(const int* __restrict__ ei0, const int* __restrict__ ei1,
                          const int* __restrict__ ei2,
                          const float* __restrict__ ev0, const float* __restrict__ ev1,
                          const float* __restrict__ ev2) {
    int e = blockIdx.x * blockDim.x + threadIdx.x;
    if (e >= ETOT) return;
    const int* ei; const float* ev; int le; int t;
    if (e < EE)          { ei = ei0; ev = ev0; le = e;           t = 0; }
    else if (e < 2 * EE) { ei = ei1; ev = ev1; le = e - EE;      t = 1; }
    else                 { ei = ei2; ev = ev2; le = e - 2 * EE;  t = 2; }
    int r   = ei[le];
    int cix = ei[EE + le];
    float v = ev[le];
    int p = atomicAdd(&g_cursor[r], 1);
    g_scol[p] = cix | (t << 28);
    g_sval[p] = v;
}

// ---------------- projection GEMM: H[c] = Xin @ Ws[c]; X0 = H ----------------
// grid: ((N+63)/64, C), block 256. Warp per row, lane owns 2 output cols.
__global__ __launch_bounds__(256) void k_proj(const float* __restrict__ xin_param,
                                              int useMid,
                                              const float* __restrict__ Ws) {
    const float* __restrict__ Xin = useMid ? (const float*)g_mid : xin_param;
    int c = blockIdx.y;
    const float* __restrict__ W = Ws + (size_t)c * HD * HD;
    __shared__ float wsm[HD * HD];  // 16 KB
    for (int i = threadIdx.x; i < HD * HD; i += 256) wsm[i] = __ldg(&W[i]);
    __syncthreads();
    int warp = threadIdx.x >> 5, lane = threadIdx.x & 31;
    int rowBase = blockIdx.x * 64;
    const float2* __restrict__ wsm2 = (const float2*)wsm;
    for (int rr = warp; rr < 64; rr += 8) {
        int row = rowBase + rr;
        if (row >= NN) break;
        float x0 = Xin[(size_t)row * HD + lane];
        float x1 = Xin[(size_t)row * HD + 32 + lane];
        float2 acc = {0.f, 0.f};
#pragma unroll
        for (int k = 0; k < HD; k++) {
            float xk = __shfl_sync(0xffffffffu, (k < 32) ? x0 : x1, k & 31);
            float2 wv = wsm2[k * 32 + lane];
            acc.x = fmaf(xk, wv.x, acc.x);
            acc.y = fmaf(xk, wv.y, acc.y);
        }
        size_t o = ((size_t)(c * NN + row)) * HD + 2 * lane;
        *(float2*)(g_H0 + o) = acc;
        *(float2*)(g_X0 + o) = acc;
    }
}

// ---------------- SpMM: Hout[c,r,:] = sum_e w_e * Hin[c,col_e,:] ----------------
// warp per (row, channel). dir=0: H0->H1, dir=1: H1->H0.
__global__ __launch_bounds__(256) void k_spmm(int dir, const float* __restrict__ layW) {
    const float* __restrict__ Hin  = dir ? g_H1 : g_H0;
    float* __restrict__       Hout = dir ? g_H0 : g_H1;
    int c = blockIdx.y;
    int warp = threadIdx.x >> 5, lane = threadIdx.x & 31;
    int r = blockIdx.x * 8 + warp;
    if (r >= NN) return;

    // softmax over T=3 for this channel
    float a0 = __ldg(&layW[c * TT + 0]);
    float a1 = __ldg(&layW[c * TT + 1]);
    float a2 = __ldg(&layW[c * TT + 2]);
    float mx = fmaxf(a0, fmaxf(a1, a2));
    float f0 = __expf(a0 - mx), f1 = __expf(a1 - mx), f2 = __expf(a2 - mx);
    float inv = 1.0f / (f0 + f1 + f2);
    f0 *= inv; f1 *= inv; f2 *= inv;

    int start = g_rowptr[r];
    int end   = g_rowptr[r + 1];
    const float* __restrict__ Hc = Hin + (size_t)c * NN * HD;
    float2 acc = {0.f, 0.f};

    for (int base = start; base < end; base += 32) {
        int e = base + lane;
        float w = 0.f;
        int ci = 0;
        if (e < end) {
            int pc  = __ldg(&g_scol[e]);
            float v = __ldg(&g_sval[e]);
            int et  = pc >> 28;
            ci = pc & 0x0FFFFFFF;
            float f = (et == 0) ? f0 : ((et == 1) ? f1 : f2);
            w = v * f;
        }
        int m = end - base;
        if (m > 32) m = 32;
        int j = 0;
        for (; j + 4 <= m; j += 4) {
            int   c0 = __shfl_sync(0xffffffffu, ci, j + 0);
            int   c1 = __shfl_sync(0xffffffffu, ci, j + 1);
            int   c2 = __shfl_sync(0xffffffffu, ci, j + 2);
            int   c3 = __shfl_sync(0xffffffffu, ci, j + 3);
            float w0 = __shfl_sync(0xffffffffu, w,  j + 0);
            float w1 = __shfl_sync(0xffffffffu, w,  j + 1);
            float w2 = __shfl_sync(0xffffffffu, w,  j + 2);
            float w3 = __shfl_sync(0xffffffffu, w,  j + 3);
            float2 h0 = *(const float2*)(Hc + (((size_t)c0) << 6) + 2 * lane);
            float2 h1 = *(const float2*)(Hc + (((size_t)c1) << 6) + 2 * lane);
            float2 h2 = *(const float2*)(Hc + (((size_t)c2) << 6) + 2 * lane);
            float2 h3 = *(const float2*)(Hc + (((size_t)c3) << 6) + 2 * lane);
            acc.x = fmaf(w0, h0.x, acc.x); acc.y = fmaf(w0, h0.y, acc.y);
            acc.x = fmaf(w1, h1.x, acc.x); acc.y = fmaf(w1, h1.y, acc.y);
            acc.x = fmaf(w2, h2.x, acc.x); acc.y = fmaf(w2, h2.y, acc.y);
            acc.x = fmaf(w3, h3.x, acc.x); acc.y = fmaf(w3, h3.y, acc.y);
        }
        for (; j < m; j++) {
            int   cj = __shfl_sync(0xffffffffu, ci, j);
            float wj = __shfl_sync(0xffffffffu, w,  j);
            float2 h = *(const float2*)(Hc + (((size_t)cj) << 6) + 2 * lane);
            acc.x = fmaf(wj, h.x, acc.x);
            acc.y = fmaf(wj, h.y, acc.y);
        }
    }
    *(float2*)(Hout + ((size_t)(c * NN + r)) * HD + 2 * lane) = acc;
}

// ---------------- fused combine + linear + relu ----------------
// reads g_X0, g_H0 (final H), computes Hm on the fly, Y = relu(Hm @ linW + b)
__global__ __launch_bounds__(256) void k_lin(const float* __restrict__ linW,
                                             const float* __restrict__ linb,
                                             float* __restrict__ outp, int useOut) {
    float* __restrict__ Y = useOut ? outp : g_mid;
    __shared__ float wsm[2 * HD * HD];  // 128x64 = 32 KB
    for (int i = threadIdx.x; i < 2 * HD * HD; i += 256) wsm[i] = __ldg(&linW[i]);
    __syncthreads();
    int warp = threadIdx.x >> 5, lane = threadIdx.x & 31;
    int rowBase = blockIdx.x * 64;
    const float2* __restrict__ wsm2 = (const float2*)wsm;
    float2 bias = {__ldg(&linb[2 * lane]), __ldg(&linb[2 * lane + 1])};
    for (int rr = warp; rr < 64; rr += 8) {
        int row = rowBase + rr;
        if (row >= NN) break;
        float xv[4];
#pragma unroll
        for (int t = 0; t < 4; t++) {
            int k = lane + 32 * t;      // k in [0,128): c = k>>6, j = k&63
            int cch = k >> 6, j = k & 63;
            size_t o = ((size_t)(cch * NN + row)) * HD + j;
            float a = g_X0[o];
            float h = g_H0[o];
            float m = 0.5f * a + 0.5f * h;
            m = m > 0.f ? m : 0.f;
            xv[t] = 0.8f * m + 0.2f * a;
        }
        float2 acc = bias;
#pragma unroll
        for (int k = 0; k < 2 * HD; k++) {
            float xk = __shfl_sync(0xffffffffu, xv[k >> 5], k & 31);
            float2 wv = wsm2[k * 32 + lane];
            acc.x = fmaf(xk, wv.x, acc.x);
            acc.y = fmaf(xk, wv.y, acc.y);
        }
        acc.x = acc.x > 0.f ? acc.x : 0.f;
        acc.y = acc.y > 0.f ? acc.y : 0.f;
        *(float2*)(Y + (size_t)row * HD + 2 * lane) = acc;
    }
}

// ---------------- launch ----------------
extern "C" void kernel_launch(void* const* d_in, const int* in_sizes, int n_in,
                              void* d_out, int out_size) {
    const float* X     = (const float*)d_in[0];
    const float* ev0   = (const float*)d_in[1];
    const float* ev1   = (const float*)d_in[2];
    const float* ev2   = (const float*)d_in[3];
    const float* Ws0   = (const float*)d_in[4];
    const float* Ws1   = (const float*)d_in[5];
    const float* lW0   = (const float*)d_in[6];
    const float* lW1   = (const float*)d_in[7];
    const float* linW0 = (const float*)d_in[8];
    const float* linb0 = (const float*)d_in[9];
    const float* linW1 = (const float*)d_in[10];
    const float* linb1 = (const float*)d_in[11];
    const int*   ei0   = (const int*)d_in[12];
    const int*   ei1   = (const int*)d_in[13];
    const int*   ei2   = (const int*)d_in[14];

    // ---- CSR build (same inputs every call -> deterministic structure) ----
    k_zero_cnt<<<(NN + 255) / 256, 256>>>();
    k_hist<<<(ETOT + 255) / 256, 256>>>(ei0, ei1, ei2);
    int nb = (NN + SCAN_CHUNK - 1) / SCAN_CHUNK;  // 13
    k_scan1<<<nb, SCAN_T>>>();
    k_scan2<<<1, 32>>>(nb);
    k_scan3<<<(NN + 255) / 256, 256>>>();
    k_scatter<<<(ETOT + 255) / 256, 256>>>(ei0, ei1, ei2, ev0, ev1, ev2);

    dim3 gp((NN + 63) / 64, CC);
    dim3 gs((NN + 7) / 8, CC);

    // ---- block 1 ----
    k_proj<<<gp, 256>>>(X, 0, Ws0);
    k_spmm<<<gs, 256>>>(0, lW0);             // layer 0: H0 -> H1
    k_spmm<<<gs, 256>>>(1, lW0 + CC * TT);   // layer 1: H1 -> H0
    k_lin<<<(NN + 63) / 64, 256>>>(linW0, linb0, nullptr, 0);   // -> g_mid

    // ---- block 2 ----
    k_proj<<<gp, 256>>>(nullptr, 1, Ws1);
    k_spmm<<<gs, 256>>>(0, lW1);
    k_spmm<<<gs, 256>>>(1, lW1 + CC * TT);
    k_lin<<<(NN + 63) / 64, 256>>>(linW1, linb1, (float*)d_out, 1);  // -> output
}

// round 7
// speedup vs baseline: 1.0758x; 1.0758x over previous
#include <cuda_runtime.h>

#define NN   50000
#define EE   300000
#define ETOT 900000
#define CC   2
#define TT   3
#define HD   64
#define CH   ((size_t)NN * HD)          // per-channel plane size
// scan config
#define SCAN_T 512
#define SCAN_I 8
#define SCAN_CHUNK (SCAN_T * SCAN_I)    // 4096

// ---------------- device scratch (static, allowed) ----------------
__device__ int   g_cnt[NN];
__device__ int   g_rowptr[NN + 1];
__device__ int   g_cursor[NN];
__device__ int   g_bsum[64];
__device__ int   g_scol[ETOT];            // col | (etype<<28)
__device__ float g_sval[ETOT];
__device__ float g_H0[(size_t)CC * NN * HD];
__device__ float g_H1[(size_t)CC * NN * HD];
__device__ float g_X0[(size_t)CC * NN * HD];
__device__ float g_mid[(size_t)NN * HD];

// ---------------- CSR build ----------------
__global__ void k_hist(const int* __restrict__ ei0, const int* __restrict__ ei1,
                       const int* __restrict__ ei2) {
    int e = blockIdx.x * blockDim.x + threadIdx.x;
    if (e >= ETOT) return;
    const int* ei; int le;
    if (e < EE)           { ei = ei0; le = e; }
    else if (e < 2 * EE)  { ei = ei1; le = e - EE; }
    else                  { ei = ei2; le = e - 2 * EE; }
    atomicAdd(&g_cnt[ei[le]], 1);
}

__global__ void k_scan1() {
    __shared__ int s[SCAN_T];
    int t = threadIdx.x;
    int base = blockIdx.x * SCAN_CHUNK + t * SCAN_I;
    int v[SCAN_I];
    int sum = 0;
#pragma unroll
    for (int i = 0; i < SCAN_I; i++) {
        int idx = base + i;
        v[i] = (idx < NN) ? g_cnt[idx] : 0;
        sum += v[i];
    }
    s[t] = sum;
    __syncthreads();
    for (int off = 1; off < SCAN_T; off <<= 1) {
        int x = (t >= off) ? s[t - off] : 0;
        __syncthreads();
        if (t >= off) s[t] += x;
        __syncthreads();
    }
    int excl = s[t] - sum;
    if (t == SCAN_T - 1) g_bsum[blockIdx.x] = s[t];
    int run = excl;
#pragma unroll
    for (int i = 0; i < SCAN_I; i++) {
        int idx = base + i;
        if (idx < NN) g_rowptr[idx] = run;
        run += v[i];
    }
}

// folds the (13-entry) block-sum prefix in as a broadcast loop; also writes
// rowptr[NN] and initializes the scatter cursor.
__global__ void k_scan3() {
    int i = blockIdx.x * blockDim.x + threadIdx.x;
    if (i >= NN) return;
    int blk = i / SCAN_CHUNK;
    int off = 0;
    for (int b = 0; b < blk; b++) off += g_bsum[b];
    int val = g_rowptr[i] + off;
    g_rowptr[i] = val;
    g_cursor[i] = val;
    if (i == 0) g_rowptr[NN] = ETOT;
}

__global__ void k_scatter(const int* __restrict__ ei0, const int* __restrict__ ei1,
                          const int* __restrict__ ei2,
                          const float* __restrict__ ev0, const float* __restrict__ ev1,
                          const float* __restrict__ ev2) {
    int e = blockIdx.x * blockDim.x + threadIdx.x;
    if (e >= ETOT) return;
    const int* ei; const float* ev; int le; int t;
    if (e < EE)          { ei = ei0; ev = ev0; le = e;           t = 0; }
    else if (e < 2 * EE) { ei = ei1; ev = ev1; le = e - EE;      t = 1; }
    else                 { ei = ei2; ev = ev2; le = e - 2 * EE;  t = 2; }
    int r   = ei[le];
    int cix = ei[EE + le];
    float v = ev[le];
    int p = atomicAdd(&g_cursor[r], 1);
    g_scol[p] = cix | (t << 28);
    g_sval[p] = v;
}

// ---------------- projection GEMM (both channels): H[c] = Xin @ Ws[c]; X0 = H ----
// grid: (N+63)/64, block 256. Warp per row, lane owns 2 output cols per channel.
__global__ __launch_bounds__(256) void k_proj(const float* __restrict__ xin_param,
                                              int useMid,
                                              const float* __restrict__ Ws) {
    const float* __restrict__ Xin = useMid ? (const float*)g_mid : xin_param;
    __shared__ float wsm[2 * HD * HD];  // 32 KB
    for (int i = threadIdx.x; i < 2 * HD * HD; i += 256) wsm[i] = __ldg(&Ws[i]);
    __syncthreads();
    int warp = threadIdx.x >> 5, lane = threadIdx.x & 31;
    int rowBase = blockIdx.x * 64;
    const float2* __restrict__ w0 = (const float2*)wsm;
    const float2* __restrict__ w1 = (const float2*)(wsm + HD * HD);
    for (int rr = warp; rr < 64; rr += 8) {
        int row = rowBase + rr;
        if (row >= NN) break;
        float x0 = Xin[(size_t)row * HD + lane];
        float x1 = Xin[(size_t)row * HD + 32 + lane];
        float2 a0 = {0.f, 0.f}, a1 = {0.f, 0.f};
#pragma unroll
        for (int k = 0; k < HD; k++) {
            float xk = __shfl_sync(0xffffffffu, (k < 32) ? x0 : x1, k & 31);
            float2 v0 = w0[k * 32 + lane];
            float2 v1 = w1[k * 32 + lane];
            a0.x = fmaf(xk, v0.x, a0.x); a0.y = fmaf(xk, v0.y, a0.y);
            a1.x = fmaf(xk, v1.x, a1.x); a1.y = fmaf(xk, v1.y, a1.y);
        }
        size_t o0 = ((size_t)row) * HD + 2 * lane;
        size_t o1 = o0 + CH;
        *(float2*)(g_H0 + o0) = a0;  *(float2*)(g_X0 + o0) = a0;
        *(float2*)(g_H1 + o1) = a1;  *(float2*)(g_X0 + o1) = a1;   // note: ch1 staged in H1? no
    }
}

// ---------------- SpMM (both channels, half-warp float4 gathers) ----------------
// warp per row. dir=0: g_H0 -> g_H1, dir=1: g_H1 -> g_H0 (both channel planes).
__global__ __launch_bounds__(256) void k_spmm(int dir, const float* __restrict__ layW) {
    const float* __restrict__ Hin  = dir ? g_H1 : g_H0;
    float* __restrict__       Hout = dir ? g_H0 : g_H1;
    int warp = threadIdx.x >> 5, lane = threadIdx.x & 31;
    int sub = lane >> 4, laneq = lane & 15;
    int r = blockIdx.x * 8 + warp;
    if (r >= NN) return;

    // softmax over T=3 for each channel
    float f0[TT], f1[TT];
    {
        float b0 = __ldg(&layW[0]), b1 = __ldg(&layW[1]), b2 = __ldg(&layW[2]);
        float mx = fmaxf(b0, fmaxf(b1, b2));
        float e0 = __expf(b0 - mx), e1 = __expf(b1 - mx), e2 = __expf(b2 - mx);
        float inv = 1.0f / (e0 + e1 + e2);
        f0[0] = e0 * inv; f0[1] = e1 * inv; f0[2] = e2 * inv;
        b0 = __ldg(&layW[3]); b1 = __ldg(&layW[4]); b2 = __ldg(&layW[5]);
        mx = fmaxf(b0, fmaxf(b1, b2));
        e0 = __expf(b0 - mx); e1 = __expf(b1 - mx); e2 = __expf(b2 - mx);
        inv = 1.0f / (e0 + e1 + e2);
        f1[0] = e0 * inv; f1[1] = e1 * inv; f1[2] = e2 * inv;
    }

    int start = g_rowptr[r];
    int end   = g_rowptr[r + 1];
    float4 acc0 = {0.f, 0.f, 0.f, 0.f};
    float4 acc1 = {0.f, 0.f, 0.f, 0.f};

    for (int base = start; base < end; base += 32) {
        int e = base + lane;
        float wa = 0.f, wb = 0.f;
        int ci = 0;
        if (e < end) {
            int pc  = __ldg(&g_scol[e]);
            float v = __ldg(&g_sval[e]);
            int et  = pc >> 28;
            ci = pc & 0x0FFFFFFF;
            float fa = (et == 0) ? f0[0] : ((et == 1) ? f0[1] : f0[2]);
            float fb = (et == 0) ? f1[0] : ((et == 1) ? f1[1] : f1[2]);
            wa = v * fa;
            wb = v * fb;
        }
        int mm = end - base;
        if (mm > 32) mm = 32;
        int mm2 = (mm + 1) & ~1;    // lanes >= mm carry w=0, so padding is safe

#define SPMM_PAIR(J)                                                          \
        {                                                                     \
            int src = (J) + sub;                                              \
            int   cj = __shfl_sync(0xffffffffu, ci, src);                     \
            float ua = __shfl_sync(0xffffffffu, wa, src);                     \
            float ub = __shfl_sync(0xffffffffu, wb, src);                     \
            float4 h0 = *((const float4*)(Hin + (((size_t)cj) << 6)) + laneq);\
            float4 h1 = *((const float4*)(Hin + CH + (((size_t)cj) << 6)) + laneq);\
            acc0.x = fmaf(ua, h0.x, acc0.x); acc0.y = fmaf(ua, h0.y, acc0.y); \
            acc0.z = fmaf(ua, h0.z, acc0.z); acc0.w = fmaf(ua, h0.w, acc0.w); \
            acc1.x = fmaf(ub, h1.x, acc1.x); acc1.y = fmaf(ub, h1.y, acc1.y); \
            acc1.z = fmaf(ub, h1.z, acc1.z); acc1.w = fmaf(ub, h1.w, acc1.w); \
        }

        int j = 0;
        for (; j + 8 <= mm2; j += 8) {
#pragma unroll
            for (int p = 0; p < 4; p++) SPMM_PAIR(j + 2 * p);
        }
        for (; j < mm2; j += 2) SPMM_PAIR(j);
#undef SPMM_PAIR
    }

    // combine the two half-warps (each accumulated every other edge)
    acc0.x += __shfl_xor_sync(0xffffffffu, acc0.x, 16);
    acc0.y += __shfl_xor_sync(0xffffffffu, acc0.y, 16);
    acc0.z += __shfl_xor_sync(0xffffffffu, acc0.z, 16);
    acc0.w += __shfl_xor_sync(0xffffffffu, acc0.w, 16);
    acc1.x += __shfl_xor_sync(0xffffffffu, acc1.x, 16);
    acc1.y += __shfl_xor_sync(0xffffffffu, acc1.y, 16);
    acc1.z += __shfl_xor_sync(0xffffffffu, acc1.z, 16);
    acc1.w += __shfl_xor_sync(0xffffffffu, acc1.w, 16);

    float4 outv = (sub == 0) ? acc0 : acc1;
    size_t off = ((size_t)sub) * CH + ((size_t)r << 6) + 4 * laneq;
    *(float4*)(Hout + off) = outv;
}

// ---------------- fused combine + linear + relu ----------------
// reads g_X0 and final H (in g_H0 after 2 layers), computes Hm on the fly,
// Y = relu(Hm @ linW + b)
__global__ __launch_bounds__(256) void k_lin(const float* __restrict__ linW,
                                             const float* __restrict__ linb,
                                             float* __restrict__ outp, int useOut) {
    float* __restrict__ Y = useOut ? outp : g_mid;
    __shared__ float wsm[2 * HD * HD];  // 128x64 = 32 KB
    for (int i = threadIdx.x; i < 2 * HD * HD; i += 256) wsm[i] = __ldg(&linW[i]);
    __syncthreads();
    int warp = threadIdx.x >> 5, lane = threadIdx.x & 31;
    int rowBase = blockIdx.x * 64;
    const float2* __restrict__ wsm2 = (const float2*)wsm;
    float2 bias = {__ldg(&linb[2 * lane]), __ldg(&linb[2 * lane + 1])};
    for (int rr = warp; rr < 64; rr += 8) {
        int row = rowBase + rr;
        if (row >= NN) break;
        float xv[4];
#pragma unroll
        for (int t = 0; t < 4; t++) {
            int k = lane + 32 * t;      // k in [0,128): c = k>>6, j = k&63
            int cch = k >> 6, j = k & 63;
            size_t o = ((size_t)cch) * CH + ((size_t)row) * HD + j;
            float a = g_X0[o];
            float h = g_H0[o];
            float m = 0.5f * a + 0.5f * h;
            m = m > 0.f ? m : 0.f;
            xv[t] = 0.8f * m + 0.2f * a;
        }
        float2 acc = bias;
#pragma unroll
        for (int k = 0; k < 2 * HD; k++) {
            float xk = __shfl_sync(0xffffffffu, xv[k >> 5], k & 31);
            float2 wv = wsm2[k * 32 + lane];
            acc.x = fmaf(xk, wv.x, acc.x);
            acc.y = fmaf(xk, wv.y, acc.y);
        }
        acc.x = acc.x > 0.f ? acc.x : 0.f;
        acc.y = acc.y > 0.f ? acc.y : 0.f;
        *(float2*)(Y + (size_t)row * HD + 2 * lane) = acc;
    }
}

// ---------------- launch ----------------
// NOTE on ping-pong: k_proj writes channel planes of the INITIAL H into g_H0
// (both channels: plane0 at g_H0, plane1 at g_H0+CH). The k_proj above had a
// bug writing ch1 into g_H1; fixed here by a tiny copy-free convention:
// k_proj must write BOTH channels into g_H0. See k_proj_fix below.

__global__ __launch_bounds__(256) void k_proj2(const float* __restrict__ xin_param,
                                               int useMid,
                                               const float* __restrict__ Ws) {
    const float* __restrict__ Xin = useMid ? (const float*)g_mid : xin_param;
    __shared__ float wsm[2 * HD * HD];
    for (int i = threadIdx.x; i < 2 * HD * HD; i += 256) wsm[i] = __ldg(&Ws[i]);
    __syncthreads();
    int warp = threadIdx.x >> 5, lane = threadIdx.x & 31;
    int rowBase = blockIdx.x * 64;
    const float2* __restrict__ w0 = (const float2*)wsm;
    const float2* __restrict__ w1 = (const float2*)(wsm + HD * HD);
    for (int rr = warp; rr < 64; rr += 8) {
        int row = rowBase + rr;
        if (row >= NN) break;
        float x0 = Xin[(size_t)row * HD + lane];
        float x1 = Xin[(size_t)row * HD + 32 + lane];
        float2 a0 = {0.f, 0.f}, a1 = {0.f, 0.f};
#pragma unroll
        for (int k = 0; k < HD; k++) {
            float xk = __shfl_sync(0xffffffffu, (k < 32) ? x0 : x1, k & 31);
            float2 v0 = w0[k * 32 + lane];
            float2 v1 = w1[k * 32 + lane];
            a0.x = fmaf(xk, v0.x, a0.x); a0.y = fmaf(xk, v0.y, a0.y);
            a1.x = fmaf(xk, v1.x, a1.x); a1.y = fmaf(xk, v1.y, a1.y);
        }
        size_t o0 = ((size_t)row) * HD + 2 * lane;
        size_t o1 = o0 + CH;
        *(float2*)(g_H0 + o0) = a0;  *(float2*)(g_X0 + o0) = a0;
        *(float2*)(g_H0 + o1) = a1;  *(float2*)(g_X0 + o1) = a1;
    }
}

extern "C" void kernel_launch(void* const* d_in, const int* in_sizes, int n_in,
                              void* d_out, int out_size) {
    const float* X     = (const float*)d_in[0];
    const float* ev0   = (const float*)d_in[1];
    const float* ev1   = (const float*)d_in[2];
    const float* ev2   = (const float*)d_in[3];
    const float* Ws0   = (const float*)d_in[4];
    const float* Ws1   = (const float*)d_in[5];
    const float* lW0   = (const float*)d_in[6];
    const float* lW1   = (const float*)d_in[7];
    const float* linW0 = (const float*)d_in[8];
    const float* linb0 = (const float*)d_in[9];
    const float* linW1 = (const float*)d_in[10];
    const float* linb1 = (const float*)d_in[11];
    const int*   ei0   = (const int*)d_in[12];
    const int*   ei1   = (const int*)d_in[13];
    const int*   ei2   = (const int*)d_in[14];

    // ---- CSR build ----
    void* cntPtr = nullptr;
    cudaGetSymbolAddress(&cntPtr, g_cnt);
    cudaMemsetAsync(cntPtr, 0, NN * sizeof(int), 0);
    k_hist<<<(ETOT + 255) / 256, 256>>>(ei0, ei1, ei2);
    int nb = (NN + SCAN_CHUNK - 1) / SCAN_CHUNK;  // 13
    k_scan1<<<nb, SCAN_T>>>();
    k_scan3<<<(NN + 255) / 256, 256>>>();
    k_scatter<<<(ETOT + 255) / 256, 256>>>(ei0, ei1, ei2, ev0, ev1, ev2);

    dim3 gp((NN + 63) / 64);
    dim3 gs((NN + 7) / 8);

    // ---- block 1 ----
    k_proj2<<<gp, 256>>>(X, 0, Ws0);
    k_spmm<<<gs, 256>>>(0, lW0);             // layer 0: H0 -> H1
    k_spmm<<<gs, 256>>>(1, lW0 + CC * TT);   // layer 1: H1 -> H0
    k_lin<<<(NN + 63) / 64, 256>>>(linW0, linb0, nullptr, 0);   // -> g_mid

    // ---- block 2 ----
    k_proj2<<<gp, 256>>>(nullptr, 1, Ws1);
    k_spmm<<<gs, 256>>>(0, lW1);
    k_spmm<<<gs, 256>>>(1, lW1 + CC * TT);
    k_lin<<<(NN + 63) / 64, 256>>>(linW1, linb1, (float*)d_out, 1);  // -> output
}